// round 14
// baseline (speedup 1.0000x reference)
#include <cuda_runtime.h>

#define KN 40
#define FN 32
#define VPW 4                 // vertices per warp
#define WPB 4                 // warps per block
#define ASTR 41               // record stride per vertex (stagger)
#define AN (VPW*ASTR)         // 164 records per array per warp
#define WSH (AN*4 + AN*4 + AN*2 + AN)   // floats per warp = 1804 (7216 B)
#define SSTR 392              // epilogue staging stride (floats, float4 aligned)

__device__ float4 g_coords4[131072];   // padded coords scratch (V <= 131072)

__device__ __forceinline__ unsigned long long pack2(float lo, float hi) {
    unsigned long long r;
    asm("mov.b64 %0, {%1,%2};" : "=l"(r) : "f"(lo), "f"(hi));
    return r;
}
__device__ __forceinline__ void unpack2(unsigned long long v, float& lo, float& hi) {
    asm("mov.b64 {%0,%1}, %2;" : "=f"(lo), "=f"(hi) : "l"(v));
}
__device__ __forceinline__ unsigned long long ffma2(unsigned long long a,
                                                    unsigned long long b,
                                                    unsigned long long c) {
    unsigned long long d;
    asm("fma.rn.f32x2 %0, %1, %2, %3;" : "=l"(d) : "l"(a), "l"(b), "l"(c));
    return d;
}

__global__ void pad_coords_kernel(const float* __restrict__ c, int V) {
    int i = blockIdx.x * blockDim.x + threadIdx.x;
    if (i < V) {
        g_coords4[i] = make_float4(c[3*i], c[3*i+1], c[3*i+2], 0.f);
    }
}

__global__ __launch_bounds__(WPB * 32, 7)   // cap regs ~72 -> 7 blocks (28 warps) per SM
void nbcov_kernel(const float* __restrict__ distsq,
                  const float* __restrict__ feats,
                  const int* __restrict__ nidx,
                  float* __restrict__ out, int V)
{
    __shared__ float smem[WPB * WSH];
    const int warp = threadIdx.x >> 5;
    const int lane = threadIdx.x & 31;
    const int vbase = (blockIdx.x * WPB + warp) * VPW;
    float* ws = smem + warp * WSH;

    float4* A4  = (float4*)ws;               // [vloc*41+k]: (w,  wx,  wy,  wz)
    float4* B4  = A4 + AN;                   // [vloc*41+k]: (wxx,wxy, wxz, wyy)
    float2* C2  = (float2*)(B4 + AN);        // [vloc*41+k]: (wyz,wzz)
    int*    fbA = (int*)(C2 + AN);           // [vloc*41+k]: ia*FN

    // ---------- prep: 160 (vertex,k) tasks; precompute full moment records ----------
    #pragma unroll
    for (int t = 0; t < 5; ++t) {
        const int id = t * 32 + lane;          // 0..159, lexicographic (vloc,k)
        const int vloc = id / KN;
        const int k = id - vloc * KN;
        const int v = vbase + vloc;
        float w = 0.f;
        int ia = 0;
        float4 c4 = make_float4(0.f, 0.f, 0.f, 0.f);
        if (v < V) {
            const int ko = vbase * KN + id;    // contiguous, coalesced
            int t_ia = nidx[ko];
            float d = distsq[ko];
            if (t_ia >= 0) { w = __expf(-10.0f * d); ia = t_ia; }
            c4 = g_coords4[ia];                // single LDG.128 gather (irreducible)
        }
        const float wx = w * c4.x, wy = w * c4.y, wz = w * c4.z;
        const int ridx = vloc * ASTR + k;
        A4[ridx]  = make_float4(w, wx, wy, wz);
        B4[ridx]  = make_float4(wx * c4.x, wx * c4.y, wx * c4.z, wy * c4.y);
        C2[ridx]  = make_float2(wy * c4.z, wz * c4.z);
        fbA[ridx] = ia * FN;
    }
    __syncwarp();

    // ---------- main: 8-lane group g = vertex vbase+g, 4 features/lane ----------
    const int g = lane >> 3;
    const int sub = lane & 7;
    const float4* ap = A4 + g * ASTR;
    const float4* bp = B4 + g * ASTR;
    const float2* cp = C2 + g * ASTR;
    const int*    fp = fbA + g * ASTR;
    const float* fbase = feats + sub * 4;

    unsigned long long P[4][5];
    #pragma unroll
    for (int c = 0; c < 4; ++c)
        #pragma unroll
        for (int j = 0; j < 5; ++j) P[c][j] = 0ull;

    // depth-4 pipelined feature gather (register ring)
    float4 f4r[4];
    f4r[0] = *(const float4*)(fbase + fp[0]);
    f4r[1] = *(const float4*)(fbase + fp[1]);
    f4r[2] = *(const float4*)(fbase + fp[2]);
    f4r[3] = *(const float4*)(fbase + fp[3]);

    #pragma unroll 8
    for (int k = 0; k < KN; ++k) {
        const float4 f4 = f4r[k & 3];
        const int kp = (k + 4 < KN) ? (k + 4) : (KN - 1);
        f4r[k & 3] = *(const float4*)(fbase + fp[kp]);     // prefetch k+4

        const ulonglong2 Aq = *(const ulonglong2*)(ap + k);    // LDS.128 bcast
        const ulonglong2 Bq = *(const ulonglong2*)(bp + k);    // LDS.128 bcast
        const unsigned long long Cq = *(const unsigned long long*)(cp + k); // LDS.64

        const unsigned long long d0 = pack2(f4.x, f4.x);
        const unsigned long long d1 = pack2(f4.y, f4.y);
        const unsigned long long d2 = pack2(f4.z, f4.z);
        const unsigned long long d3 = pack2(f4.w, f4.w);

        P[0][0] = ffma2(d0, Aq.x, P[0][0]);
        P[0][1] = ffma2(d0, Aq.y, P[0][1]);
        P[0][2] = ffma2(d0, Bq.x, P[0][2]);
        P[0][3] = ffma2(d0, Bq.y, P[0][3]);
        P[0][4] = ffma2(d0, Cq,   P[0][4]);

        P[1][0] = ffma2(d1, Aq.x, P[1][0]);
        P[1][1] = ffma2(d1, Aq.y, P[1][1]);
        P[1][2] = ffma2(d1, Bq.x, P[1][2]);
        P[1][3] = ffma2(d1, Bq.y, P[1][3]);
        P[1][4] = ffma2(d1, Cq,   P[1][4]);

        P[2][0] = ffma2(d2, Aq.x, P[2][0]);
        P[2][1] = ffma2(d2, Aq.y, P[2][1]);
        P[2][2] = ffma2(d2, Bq.x, P[2][2]);
        P[2][3] = ffma2(d2, Bq.y, P[2][3]);
        P[2][4] = ffma2(d2, Cq,   P[2][4]);

        P[3][0] = ffma2(d3, Aq.x, P[3][0]);
        P[3][1] = ffma2(d3, Aq.y, P[3][1]);
        P[3][2] = ffma2(d3, Bq.x, P[3][2]);
        P[3][3] = ffma2(d3, Bq.y, P[3][3]);
        P[3][4] = ffma2(d3, Cq,   P[3][4]);
    }

    // ---------- normalize + center into per-lane contiguous blocks ----------
    float cv[36];   // features 4*sub..4*sub+3 : 36 contiguous output floats
    float mn[12];
    #pragma unroll
    for (int c = 0; c < 4; ++c) {
        float S0, S1, S2, S3, S4, S5, S6, S7, S8, S9;
        unpack2(P[c][0], S0, S1);
        unpack2(P[c][1], S2, S3);
        unpack2(P[c][2], S4, S5);
        unpack2(P[c][3], S6, S7);
        unpack2(P[c][4], S8, S9);

        const float inv = __fdividef(1.0f, S0 + 1e-3f);
        const float mx = S1 * inv, my = S2 * inv, mz = S3 * inv;
        cv[c*9+0] = fmaf(-mx, mx, S4 * inv);
        cv[c*9+1] = fmaf(-mx, my, S5 * inv);
        cv[c*9+2] = fmaf(-mx, mz, S6 * inv);
        cv[c*9+4] = fmaf(-my, my, S7 * inv);
        cv[c*9+5] = fmaf(-my, mz, S8 * inv);
        cv[c*9+8] = fmaf(-mz, mz, S9 * inv);
        cv[c*9+3] = cv[c*9+1];
        cv[c*9+6] = cv[c*9+2];
        cv[c*9+7] = cv[c*9+5];
        mn[c*3+0] = mx; mn[c*3+1] = my; mn[c*3+2] = mz;
    }

    // ---------- two staging rounds: vertices {0,1} then {2,3} ----------
    #pragma unroll
    for (int round = 0; round < 2; ++round) {
        __syncwarp();
        if ((g >> 1) == round) {
            float* st = ws + (g & 1) * SSTR;
            float4* stc = (float4*)(st + 36 * sub);       // 16B aligned
            #pragma unroll
            for (int q = 0; q < 9; ++q)
                stc[q] = *(const float4*)(cv + 4 * q);
            float4* stm = (float4*)(st + 288 + 12 * sub);
            #pragma unroll
            for (int q = 0; q < 3; ++q)
                stm[q] = *(const float4*)(mn + 4 * q);
        }
        __syncwarp();
        // warp-wide coalesced copy of 768 floats (2 vertices)
        float* outp = out + (size_t)(vbase + 2 * round) * 384;
        #pragma unroll
        for (int r = 0; r < 6; ++r) {
            const int e = r * 128 + lane * 4;
            const int gv = (e >= 384) ? 1 : 0;
            if (vbase + 2 * round + gv < V) {
                float4 val = *(const float4*)(ws + gv * SSTR + (e - gv * 384));
                *(float4*)(outp + e) = val;
            }
        }
    }
}

extern "C" void kernel_launch(void* const* d_in, const int* in_sizes, int n_in,
                              void* d_out, int out_size) {
    const float* coords = (const float*)d_in[0];   // V x 3
    const float* distsq = (const float*)d_in[1];   // V x 40
    const float* feats  = (const float*)d_in[2];   // V x 32
    const int*   nidx   = (const int*)d_in[3];     // V x 40
    float* out = (float*)d_out;                    // V x 384
    const int V = in_sizes[0] / 3;

    pad_coords_kernel<<<(V + 255) / 256, 256>>>(coords, V);

    const int vpb = VPW * WPB;                     // 16 vertices per block
    nbcov_kernel<<<(V + vpb - 1) / vpb, WPB * 32>>>(distsq, feats, nidx, out, V);
}

// round 15
// speedup vs baseline: 1.1044x; 1.1044x over previous
#include <cuda_runtime.h>

#define KN 40
#define FN 32
#define VPW 4                 // vertices per warp
#define WPB 4                 // warps per block
#define ASTR 41               // record stride per vertex (stagger)
#define AN (VPW*ASTR)         // 164 records per array per warp
#define WSH (AN*4 + AN*4 + AN*2 + AN)   // floats per warp = 1804 (7216 B)
#define SSTR 392              // epilogue staging stride (floats, float4 aligned)

__device__ float4 g_coords4[131072];   // padded coords scratch (V <= 131072)

__device__ __forceinline__ unsigned long long pack2(float lo, float hi) {
    unsigned long long r;
    asm("mov.b64 %0, {%1,%2};" : "=l"(r) : "f"(lo), "f"(hi));
    return r;
}
__device__ __forceinline__ void unpack2(unsigned long long v, float& lo, float& hi) {
    asm("mov.b64 {%0,%1}, %2;" : "=f"(lo), "=f"(hi) : "l"(v));
}
__device__ __forceinline__ unsigned long long ffma2(unsigned long long a,
                                                    unsigned long long b,
                                                    unsigned long long c) {
    unsigned long long d;
    asm("fma.rn.f32x2 %0, %1, %2, %3;" : "=l"(d) : "l"(a), "l"(b), "l"(c));
    return d;
}

__global__ void pad_coords_kernel(const float* __restrict__ c, int V) {
    int i = blockIdx.x * blockDim.x + threadIdx.x;
    if (i < V) {
        g_coords4[i] = make_float4(c[3*i], c[3*i+1], c[3*i+2], 0.f);
    }
}

__global__ __launch_bounds__(WPB * 32, 7)   // cap 72 regs; ring slimmed so no spill expected
void nbcov_kernel(const float* __restrict__ distsq,
                  const float* __restrict__ feats,
                  const int* __restrict__ nidx,
                  float* __restrict__ out, int V)
{
    __shared__ float smem[WPB * WSH];
    const int warp = threadIdx.x >> 5;
    const int lane = threadIdx.x & 31;
    const int vbase = (blockIdx.x * WPB + warp) * VPW;
    float* ws = smem + warp * WSH;

    float4* A4  = (float4*)ws;               // [vloc*41+k]: (w,  wx,  wy,  wz)
    float4* B4  = A4 + AN;                   // [vloc*41+k]: (wxx,wxy, wxz, wyy)
    float2* C2  = (float2*)(B4 + AN);        // [vloc*41+k]: (wyz,wzz)
    int*    fbA = (int*)(C2 + AN);           // [vloc*41+k]: ia*FN

    // ---------- prep: 160 (vertex,k) tasks; precompute full moment records ----------
    #pragma unroll
    for (int t = 0; t < 5; ++t) {
        const int id = t * 32 + lane;          // 0..159, lexicographic (vloc,k)
        const int vloc = id / KN;
        const int k = id - vloc * KN;
        const int v = vbase + vloc;
        float w = 0.f;
        int ia = 0;
        float4 c4 = make_float4(0.f, 0.f, 0.f, 0.f);
        if (v < V) {
            const int ko = vbase * KN + id;    // contiguous, coalesced
            int t_ia = nidx[ko];
            float d = distsq[ko];
            if (t_ia >= 0) { w = __expf(-10.0f * d); ia = t_ia; }
            c4 = g_coords4[ia];                // single LDG.128 gather (irreducible)
        }
        const float wx = w * c4.x, wy = w * c4.y, wz = w * c4.z;
        const int ridx = vloc * ASTR + k;
        A4[ridx]  = make_float4(w, wx, wy, wz);
        B4[ridx]  = make_float4(wx * c4.x, wx * c4.y, wx * c4.z, wy * c4.y);
        C2[ridx]  = make_float2(wy * c4.z, wz * c4.z);
        fbA[ridx] = ia * FN;
    }
    __syncwarp();

    // ---------- main: 8-lane group g = vertex vbase+g, 4 features/lane ----------
    const int g = lane >> 3;
    const int sub = lane & 7;
    const float4* ap = A4 + g * ASTR;
    const float4* bp = B4 + g * ASTR;
    const float2* cp = C2 + g * ASTR;
    const int*    fp = fbA + g * ASTR;
    const float* fbase = feats + sub * 4;

    unsigned long long P[4][5];
    #pragma unroll
    for (int c = 0; c < 4; ++c)
        #pragma unroll
        for (int j = 0; j < 5; ++j) P[c][j] = 0ull;

    // depth-2 pipelined feature gather (register ring, 8 regs)
    float4 f4r[2];
    f4r[0] = *(const float4*)(fbase + fp[0]);
    f4r[1] = *(const float4*)(fbase + fp[1]);

    #pragma unroll 8
    for (int k = 0; k < KN; ++k) {
        const float4 f4 = f4r[k & 1];
        const int kp = (k + 2 < KN) ? (k + 2) : (KN - 1);
        f4r[k & 1] = *(const float4*)(fbase + fp[kp]);     // prefetch k+2

        const ulonglong2 Aq = *(const ulonglong2*)(ap + k);    // LDS.128 bcast
        const ulonglong2 Bq = *(const ulonglong2*)(bp + k);    // LDS.128 bcast
        const unsigned long long Cq = *(const unsigned long long*)(cp + k); // LDS.64

        const unsigned long long d0 = pack2(f4.x, f4.x);
        const unsigned long long d1 = pack2(f4.y, f4.y);
        const unsigned long long d2 = pack2(f4.z, f4.z);
        const unsigned long long d3 = pack2(f4.w, f4.w);

        P[0][0] = ffma2(d0, Aq.x, P[0][0]);
        P[0][1] = ffma2(d0, Aq.y, P[0][1]);
        P[0][2] = ffma2(d0, Bq.x, P[0][2]);
        P[0][3] = ffma2(d0, Bq.y, P[0][3]);
        P[0][4] = ffma2(d0, Cq,   P[0][4]);

        P[1][0] = ffma2(d1, Aq.x, P[1][0]);
        P[1][1] = ffma2(d1, Aq.y, P[1][1]);
        P[1][2] = ffma2(d1, Bq.x, P[1][2]);
        P[1][3] = ffma2(d1, Bq.y, P[1][3]);
        P[1][4] = ffma2(d1, Cq,   P[1][4]);

        P[2][0] = ffma2(d2, Aq.x, P[2][0]);
        P[2][1] = ffma2(d2, Aq.y, P[2][1]);
        P[2][2] = ffma2(d2, Bq.x, P[2][2]);
        P[2][3] = ffma2(d2, Bq.y, P[2][3]);
        P[2][4] = ffma2(d2, Cq,   P[2][4]);

        P[3][0] = ffma2(d3, Aq.x, P[3][0]);
        P[3][1] = ffma2(d3, Aq.y, P[3][1]);
        P[3][2] = ffma2(d3, Bq.x, P[3][2]);
        P[3][3] = ffma2(d3, Bq.y, P[3][3]);
        P[3][4] = ffma2(d3, Cq,   P[3][4]);
    }

    // ---------- normalize + center into per-lane contiguous blocks ----------
    float cv[36];   // features 4*sub..4*sub+3 : 36 contiguous output floats
    float mn[12];
    #pragma unroll
    for (int c = 0; c < 4; ++c) {
        float S0, S1, S2, S3, S4, S5, S6, S7, S8, S9;
        unpack2(P[c][0], S0, S1);
        unpack2(P[c][1], S2, S3);
        unpack2(P[c][2], S4, S5);
        unpack2(P[c][3], S6, S7);
        unpack2(P[c][4], S8, S9);

        const float inv = __fdividef(1.0f, S0 + 1e-3f);
        const float mx = S1 * inv, my = S2 * inv, mz = S3 * inv;
        cv[c*9+0] = fmaf(-mx, mx, S4 * inv);
        cv[c*9+1] = fmaf(-mx, my, S5 * inv);
        cv[c*9+2] = fmaf(-mx, mz, S6 * inv);
        cv[c*9+4] = fmaf(-my, my, S7 * inv);
        cv[c*9+5] = fmaf(-my, mz, S8 * inv);
        cv[c*9+8] = fmaf(-mz, mz, S9 * inv);
        cv[c*9+3] = cv[c*9+1];
        cv[c*9+6] = cv[c*9+2];
        cv[c*9+7] = cv[c*9+5];
        mn[c*3+0] = mx; mn[c*3+1] = my; mn[c*3+2] = mz;
    }

    // ---------- two staging rounds: vertices {0,1} then {2,3} ----------
    #pragma unroll
    for (int round = 0; round < 2; ++round) {
        __syncwarp();
        if ((g >> 1) == round) {
            float* st = ws + (g & 1) * SSTR;
            float4* stc = (float4*)(st + 36 * sub);       // 16B aligned
            #pragma unroll
            for (int q = 0; q < 9; ++q)
                stc[q] = *(const float4*)(cv + 4 * q);
            float4* stm = (float4*)(st + 288 + 12 * sub);
            #pragma unroll
            for (int q = 0; q < 3; ++q)
                stm[q] = *(const float4*)(mn + 4 * q);
        }
        __syncwarp();
        // warp-wide coalesced copy of 768 floats (2 vertices)
        float* outp = out + (size_t)(vbase + 2 * round) * 384;
        #pragma unroll
        for (int r = 0; r < 6; ++r) {
            const int e = r * 128 + lane * 4;
            const int gv = (e >= 384) ? 1 : 0;
            if (vbase + 2 * round + gv < V) {
                float4 val = *(const float4*)(ws + gv * SSTR + (e - gv * 384));
                *(float4*)(outp + e) = val;
            }
        }
    }
}

extern "C" void kernel_launch(void* const* d_in, const int* in_sizes, int n_in,
                              void* d_out, int out_size) {
    const float* coords = (const float*)d_in[0];   // V x 3
    const float* distsq = (const float*)d_in[1];   // V x 40
    const float* feats  = (const float*)d_in[2];   // V x 32
    const int*   nidx   = (const int*)d_in[3];     // V x 40
    float* out = (float*)d_out;                    // V x 384
    const int V = in_sizes[0] / 3;

    pad_coords_kernel<<<(V + 255) / 256, 256>>>(coords, V);

    const int vpb = VPW * WPB;                     // 16 vertices per block
    nbcov_kernel<<<(V + vpb - 1) / vpb, WPB * 32>>>(distsq, feats, nidx, out, V);
}

// round 16
// speedup vs baseline: 1.5649x; 1.4170x over previous
#include <cuda_runtime.h>

#define KN 40
#define FN 32
#define VPW 4                 // vertices per warp
#define WPB 4                 // warps per block
#define ASTR 41               // record stride per vertex (stagger)
#define AN (VPW*ASTR)         // 164 records per array per warp
#define FSTR 45               // fb stride per vertex (40 + 4 pad + 1 stagger)
#define WSH (AN*4 + AN*4 + AN*2 + VPW*FSTR)   // floats per warp = 1820
#define SSTR 392              // epilogue staging stride (floats, float4 aligned)

__device__ float4 g_coords4[131072];   // padded coords scratch (V <= 131072)

__device__ __forceinline__ unsigned long long pack2(float lo, float hi) {
    unsigned long long r;
    asm("mov.b64 %0, {%1,%2};" : "=l"(r) : "f"(lo), "f"(hi));
    return r;
}
__device__ __forceinline__ void unpack2(unsigned long long v, float& lo, float& hi) {
    asm("mov.b64 {%0,%1}, %2;" : "=f"(lo), "=f"(hi) : "l"(v));
}
__device__ __forceinline__ unsigned long long ffma2(unsigned long long a,
                                                    unsigned long long b,
                                                    unsigned long long c) {
    unsigned long long d;
    asm("fma.rn.f32x2 %0, %1, %2, %3;" : "=l"(d) : "l"(a), "l"(b), "l"(c));
    return d;
}

__global__ void pad_coords_kernel(const float* __restrict__ c, int V) {
    int i = blockIdx.x * blockDim.x + threadIdx.x;
    if (i < V) {
        g_coords4[i] = make_float4(c[3*i], c[3*i+1], c[3*i+2], 0.f);
    }
}

__global__ __launch_bounds__(WPB * 32)      // natural regs (R15 proved caps hurt)
void nbcov_kernel(const float* __restrict__ distsq,
                  const float* __restrict__ feats,
                  const int* __restrict__ nidx,
                  float* __restrict__ out, int V)
{
    __shared__ float smem[WPB * WSH];
    const int warp = threadIdx.x >> 5;
    const int lane = threadIdx.x & 31;
    const int vbase = (blockIdx.x * WPB + warp) * VPW;
    float* ws = smem + warp * WSH;

    float4* A4  = (float4*)ws;               // [vloc*41+k]: (w,  wx,  wy,  wz)
    float4* B4  = A4 + AN;                   // [vloc*41+k]: (wxx,wxy, wxz, wyy)
    float2* C2  = (float2*)(B4 + AN);        // [vloc*41+k]: (wyz,wzz)
    int*    fbA = (int*)(C2 + AN);           // [vloc*45+k]: ia*FN (padded to 44/vertex)

    // ---------- prep: batched-latency version ----------
    {
        const int kolim = V * KN - 1;
        const int base = vbase * KN + lane;
        // phase A: 10 independent LDG.32
        int   ian[5];
        float dd[5];
        #pragma unroll
        for (int t = 0; t < 5; ++t) {
            const int ko = min(base + t * 32, kolim);
            ian[t] = nidx[ko];
            dd[t]  = distsq[ko];
        }
        // phase B: 5 independent LDG.128 gathers
        float4 c4[5];
        int iac[5];
        #pragma unroll
        for (int t = 0; t < 5; ++t) {
            iac[t] = (ian[t] >= 0) ? ian[t] : 0;
            c4[t] = g_coords4[iac[t]];
        }
        // phase C: compute + STS
        #pragma unroll
        for (int t = 0; t < 5; ++t) {
            const int id = t * 32 + lane;          // 0..159, lexicographic (vloc,k)
            const int vloc = id / KN;
            const int k = id - vloc * KN;
            const float w = (ian[t] >= 0) ? __expf(-10.0f * dd[t]) : 0.0f;
            const float wx = w * c4[t].x, wy = w * c4[t].y, wz = w * c4[t].z;
            const int ridx = vloc * ASTR + k;
            A4[ridx] = make_float4(w, wx, wy, wz);
            B4[ridx] = make_float4(wx * c4[t].x, wx * c4[t].y, wx * c4[t].z, wy * c4[t].y);
            C2[ridx] = make_float2(wy * c4[t].z, wz * c4[t].z);
            fbA[vloc * FSTR + k] = iac[t] * FN;
        }
        // pad fb slots k=40..43 per vertex (safe address 0 for unconditional prefetch)
        if (lane < 16) {
            fbA[(lane >> 2) * FSTR + KN + (lane & 3)] = 0;
        }
    }
    __syncwarp();

    // ---------- main: 8-lane group g = vertex vbase+g, 4 features/lane ----------
    const int g = lane >> 3;
    const int sub = lane & 7;
    const float4* ap = A4 + g * ASTR;
    const float4* bp = B4 + g * ASTR;
    const float2* cp = C2 + g * ASTR;
    const int*    fp = fbA + g * FSTR;
    const float* fbase = feats + sub * 4;

    unsigned long long P[4][5];
    #pragma unroll
    for (int c = 0; c < 4; ++c)
        #pragma unroll
        for (int j = 0; j < 5; ++j) P[c][j] = 0ull;

    // depth-4 pipelined feature gather (register ring, unconditional via fb padding)
    float4 f4r[4];
    f4r[0] = *(const float4*)(fbase + fp[0]);
    f4r[1] = *(const float4*)(fbase + fp[1]);
    f4r[2] = *(const float4*)(fbase + fp[2]);
    f4r[3] = *(const float4*)(fbase + fp[3]);

    #pragma unroll 8
    for (int k = 0; k < KN; ++k) {
        const float4 f4 = f4r[k & 3];
        f4r[k & 3] = *(const float4*)(fbase + fp[k + 4]);   // prefetch k+4 (pad-safe)

        const ulonglong2 Aq = *(const ulonglong2*)(ap + k);    // LDS.128 bcast
        const ulonglong2 Bq = *(const ulonglong2*)(bp + k);    // LDS.128 bcast
        const unsigned long long Cq = *(const unsigned long long*)(cp + k); // LDS.64

        const unsigned long long d0 = pack2(f4.x, f4.x);
        const unsigned long long d1 = pack2(f4.y, f4.y);
        const unsigned long long d2 = pack2(f4.z, f4.z);
        const unsigned long long d3 = pack2(f4.w, f4.w);

        P[0][0] = ffma2(d0, Aq.x, P[0][0]);
        P[0][1] = ffma2(d0, Aq.y, P[0][1]);
        P[0][2] = ffma2(d0, Bq.x, P[0][2]);
        P[0][3] = ffma2(d0, Bq.y, P[0][3]);
        P[0][4] = ffma2(d0, Cq,   P[0][4]);

        P[1][0] = ffma2(d1, Aq.x, P[1][0]);
        P[1][1] = ffma2(d1, Aq.y, P[1][1]);
        P[1][2] = ffma2(d1, Bq.x, P[1][2]);
        P[1][3] = ffma2(d1, Bq.y, P[1][3]);
        P[1][4] = ffma2(d1, Cq,   P[1][4]);

        P[2][0] = ffma2(d2, Aq.x, P[2][0]);
        P[2][1] = ffma2(d2, Aq.y, P[2][1]);
        P[2][2] = ffma2(d2, Bq.x, P[2][2]);
        P[2][3] = ffma2(d2, Bq.y, P[2][3]);
        P[2][4] = ffma2(d2, Cq,   P[2][4]);

        P[3][0] = ffma2(d3, Aq.x, P[3][0]);
        P[3][1] = ffma2(d3, Aq.y, P[3][1]);
        P[3][2] = ffma2(d3, Bq.x, P[3][2]);
        P[3][3] = ffma2(d3, Bq.y, P[3][3]);
        P[3][4] = ffma2(d3, Cq,   P[3][4]);
    }

    // ---------- normalize + center into per-lane contiguous blocks ----------
    float cv[36];   // features 4*sub..4*sub+3 : 36 contiguous output floats
    float mn[12];
    #pragma unroll
    for (int c = 0; c < 4; ++c) {
        float S0, S1, S2, S3, S4, S5, S6, S7, S8, S9;
        unpack2(P[c][0], S0, S1);
        unpack2(P[c][1], S2, S3);
        unpack2(P[c][2], S4, S5);
        unpack2(P[c][3], S6, S7);
        unpack2(P[c][4], S8, S9);

        const float inv = __fdividef(1.0f, S0 + 1e-3f);
        const float mx = S1 * inv, my = S2 * inv, mz = S3 * inv;
        cv[c*9+0] = fmaf(-mx, mx, S4 * inv);
        cv[c*9+1] = fmaf(-mx, my, S5 * inv);
        cv[c*9+2] = fmaf(-mx, mz, S6 * inv);
        cv[c*9+4] = fmaf(-my, my, S7 * inv);
        cv[c*9+5] = fmaf(-my, mz, S8 * inv);
        cv[c*9+8] = fmaf(-mz, mz, S9 * inv);
        cv[c*9+3] = cv[c*9+1];
        cv[c*9+6] = cv[c*9+2];
        cv[c*9+7] = cv[c*9+5];
        mn[c*3+0] = mx; mn[c*3+1] = my; mn[c*3+2] = mz;
    }

    // ---------- two staging rounds: vertices {0,1} then {2,3} ----------
    #pragma unroll
    for (int round = 0; round < 2; ++round) {
        __syncwarp();
        if ((g >> 1) == round) {
            float* st = ws + (g & 1) * SSTR;
            float4* stc = (float4*)(st + 36 * sub);       // 16B aligned
            #pragma unroll
            for (int q = 0; q < 9; ++q)
                stc[q] = *(const float4*)(cv + 4 * q);
            float4* stm = (float4*)(st + 288 + 12 * sub);
            #pragma unroll
            for (int q = 0; q < 3; ++q)
                stm[q] = *(const float4*)(mn + 4 * q);
        }
        __syncwarp();
        // warp-wide coalesced copy of 768 floats (2 vertices)
        float* outp = out + (size_t)(vbase + 2 * round) * 384;
        #pragma unroll
        for (int r = 0; r < 6; ++r) {
            const int e = r * 128 + lane * 4;
            const int gv = (e >= 384) ? 1 : 0;
            if (vbase + 2 * round + gv < V) {
                float4 val = *(const float4*)(ws + gv * SSTR + (e - gv * 384));
                *(float4*)(outp + e) = val;
            }
        }
    }
}

extern "C" void kernel_launch(void* const* d_in, const int* in_sizes, int n_in,
                              void* d_out, int out_size) {
    const float* coords = (const float*)d_in[0];   // V x 3
    const float* distsq = (const float*)d_in[1];   // V x 40
    const float* feats  = (const float*)d_in[2];   // V x 32
    const int*   nidx   = (const int*)d_in[3];     // V x 40
    float* out = (float*)d_out;                    // V x 384
    const int V = in_sizes[0] / 3;

    pad_coords_kernel<<<(V + 255) / 256, 256>>>(coords, V);

    const int vpb = VPW * WPB;                     // 16 vertices per block
    nbcov_kernel<<<(V + vpb - 1) / vpb, WPB * 32>>>(distsq, feats, nidx, out, V);
}

// round 17
// speedup vs baseline: 1.6705x; 1.0674x over previous
#include <cuda_runtime.h>

#define KN 40
#define FN 32
#define VPW 4                 // vertices per warp
#define WPB 4                 // warps per block
#define ASTR_A 41             // A-record stride per vertex (float4)
#define ASTR_R 45             // R-record stride per vertex (float4, 40 + 4 pad + stagger)
#define AN_A (VPW*ASTR_A)     // 164
#define AN_R (VPW*ASTR_R)     // 180
#define WSH ((AN_A + AN_R)*4) // floats per warp = 1376 (5504 B)
#define SSTR 392              // epilogue staging stride (floats, float4 aligned)

__device__ float4 g_coords4[131072];   // padded coords scratch (V <= 131072)

__device__ __forceinline__ unsigned long long pack2(float lo, float hi) {
    unsigned long long r;
    asm("mov.b64 %0, {%1,%2};" : "=l"(r) : "f"(lo), "f"(hi));
    return r;
}
__device__ __forceinline__ void unpack2(unsigned long long v, float& lo, float& hi) {
    asm("mov.b64 {%0,%1}, %2;" : "=f"(lo), "=f"(hi) : "l"(v));
}
__device__ __forceinline__ unsigned long long ffma2(unsigned long long a,
                                                    unsigned long long b,
                                                    unsigned long long c) {
    unsigned long long d;
    asm("fma.rn.f32x2 %0, %1, %2, %3;" : "=l"(d) : "l"(a), "l"(b), "l"(c));
    return d;
}
__device__ __forceinline__ unsigned long long mul2(unsigned long long a,
                                                   unsigned long long b) {
    unsigned long long d;
    asm("mul.rn.f32x2 %0, %1, %2;" : "=l"(d) : "l"(a), "l"(b));
    return d;
}

__global__ void pad_coords_kernel(const float* __restrict__ c, int V) {
    int i = blockIdx.x * blockDim.x + threadIdx.x;
    if (i < V) {
        g_coords4[i] = make_float4(c[3*i], c[3*i+1], c[3*i+2], 0.f);
    }
}

__global__ __launch_bounds__(WPB * 32, 6)   // mild cap (85) = natural regime
void nbcov_kernel(const float* __restrict__ distsq,
                  const float* __restrict__ feats,
                  const int* __restrict__ nidx,
                  float* __restrict__ out, int V)
{
    __shared__ float smem[WPB * WSH];
    const int warp = threadIdx.x >> 5;
    const int lane = threadIdx.x & 31;
    const int vbase = (blockIdx.x * WPB + warp) * VPW;
    float* ws = smem + warp * WSH;

    float4* A4 = (float4*)ws;             // [vloc*41+k]: (w,  wx, wy, wz)
    float4* R4 = A4 + AN_A;               // [vloc*45+k]: (x, y, z, fb-bits)

    // ---------- prep: batched-latency (R16 structure), slim records ----------
    {
        const int kolim = V * KN - 1;
        const int base = vbase * KN + lane;
        int   ian[5];
        float dd[5];
        #pragma unroll
        for (int t = 0; t < 5; ++t) {
            const int ko = min(base + t * 32, kolim);
            ian[t] = nidx[ko];
            dd[t]  = distsq[ko];
        }
        float4 c4[5];
        int iac[5];
        #pragma unroll
        for (int t = 0; t < 5; ++t) {
            iac[t] = (ian[t] >= 0) ? ian[t] : 0;
            c4[t] = g_coords4[iac[t]];
        }
        #pragma unroll
        for (int t = 0; t < 5; ++t) {
            const int id = t * 32 + lane;          // 0..159, lexicographic (vloc,k)
            const int vloc = id / KN;
            const int k = id - vloc * KN;
            const float w = (ian[t] >= 0) ? __expf(-10.0f * dd[t]) : 0.0f;
            A4[vloc * ASTR_A + k] = make_float4(w, w * c4[t].x, w * c4[t].y, w * c4[t].z);
            R4[vloc * ASTR_R + k] = make_float4(c4[t].x, c4[t].y, c4[t].z,
                                                __int_as_float(iac[t] * FN));
        }
        // pad fb slots k=40..43 per vertex (safe bits 0 for unconditional prefetch)
        if (lane < 16) {
            ((float*)&R4[(lane >> 2) * ASTR_R + KN + (lane & 3)])[3] = __int_as_float(0);
        }
    }
    __syncwarp();

    // ---------- main: 8-lane group g = vertex vbase+g, 4 features/lane ----------
    const int g = lane >> 3;
    const int sub = lane & 7;
    const float4* af = A4 + g * ASTR_A;
    const float4* rf = R4 + g * ASTR_R;
    const float*  rw = (const float*)rf + 3;      // .w lane of R records
    const float* fbase = feats + sub * 4;

    unsigned long long P[4][5];
    #pragma unroll
    for (int c = 0; c < 4; ++c)
        #pragma unroll
        for (int j = 0; j < 5; ++j) P[c][j] = 0ull;

    // depth-4 pipelined feature gather (register ring, unconditional via fb padding)
    float4 f4r[4];
    #pragma unroll
    for (int j = 0; j < 4; ++j)
        f4r[j] = *(const float4*)(fbase + __float_as_int(rw[j * 4]));

    #pragma unroll 8
    for (int k = 0; k < KN; ++k) {
        const float4 f4 = f4r[k & 3];
        f4r[k & 3] = *(const float4*)(fbase + __float_as_int(rw[(k + 4) * 4])); // prefetch

        const float4 Af = af[k];                         // LDS.128 bcast (w,wx,wy,wz)
        const float4 Rf = rf[k];                         // LDS.128 bcast (x,y,z,fb)
        const float w = Af.x, wx = Af.y, wy = Af.z, wz = Af.w;
        const float x = Rf.x, y = Rf.y, z = Rf.z;

        const unsigned long long M0 = pack2(w,  wx);
        const unsigned long long M1 = pack2(wy, wz);
        const unsigned long long M2 = mul2(pack2(wx, wx), pack2(x, y));  // (wxx,wxy)
        const unsigned long long M3 = mul2(pack2(wx, wy), pack2(z, y));  // (wxz,wyy)
        const unsigned long long M4 = mul2(M1,            pack2(z, z));  // (wyz,wzz)

        const unsigned long long d0 = pack2(f4.x, f4.x);
        const unsigned long long d1 = pack2(f4.y, f4.y);
        const unsigned long long d2 = pack2(f4.z, f4.z);
        const unsigned long long d3 = pack2(f4.w, f4.w);

        P[0][0] = ffma2(d0, M0, P[0][0]);
        P[0][1] = ffma2(d0, M1, P[0][1]);
        P[0][2] = ffma2(d0, M2, P[0][2]);
        P[0][3] = ffma2(d0, M3, P[0][3]);
        P[0][4] = ffma2(d0, M4, P[0][4]);

        P[1][0] = ffma2(d1, M0, P[1][0]);
        P[1][1] = ffma2(d1, M1, P[1][1]);
        P[1][2] = ffma2(d1, M2, P[1][2]);
        P[1][3] = ffma2(d1, M3, P[1][3]);
        P[1][4] = ffma2(d1, M4, P[1][4]);

        P[2][0] = ffma2(d2, M0, P[2][0]);
        P[2][1] = ffma2(d2, M1, P[2][1]);
        P[2][2] = ffma2(d2, M2, P[2][2]);
        P[2][3] = ffma2(d2, M3, P[2][3]);
        P[2][4] = ffma2(d2, M4, P[2][4]);

        P[3][0] = ffma2(d3, M0, P[3][0]);
        P[3][1] = ffma2(d3, M1, P[3][1]);
        P[3][2] = ffma2(d3, M2, P[3][2]);
        P[3][3] = ffma2(d3, M3, P[3][3]);
        P[3][4] = ffma2(d3, M4, P[3][4]);
    }

    // ---------- normalize + center into per-lane contiguous blocks ----------
    float cv[36];   // features 4*sub..4*sub+3 : 36 contiguous output floats
    float mn[12];
    #pragma unroll
    for (int c = 0; c < 4; ++c) {
        float S0, S1, S2, S3, S4, S5, S6, S7, S8, S9;
        unpack2(P[c][0], S0, S1);
        unpack2(P[c][1], S2, S3);
        unpack2(P[c][2], S4, S5);
        unpack2(P[c][3], S6, S7);
        unpack2(P[c][4], S8, S9);

        const float inv = __fdividef(1.0f, S0 + 1e-3f);
        const float mx = S1 * inv, my = S2 * inv, mz = S3 * inv;
        cv[c*9+0] = fmaf(-mx, mx, S4 * inv);
        cv[c*9+1] = fmaf(-mx, my, S5 * inv);
        cv[c*9+2] = fmaf(-mx, mz, S6 * inv);
        cv[c*9+4] = fmaf(-my, my, S7 * inv);
        cv[c*9+5] = fmaf(-my, mz, S8 * inv);
        cv[c*9+8] = fmaf(-mz, mz, S9 * inv);
        cv[c*9+3] = cv[c*9+1];
        cv[c*9+6] = cv[c*9+2];
        cv[c*9+7] = cv[c*9+5];
        mn[c*3+0] = mx; mn[c*3+1] = my; mn[c*3+2] = mz;
    }

    // ---------- two staging rounds: vertices {0,1} then {2,3} ----------
    #pragma unroll
    for (int round = 0; round < 2; ++round) {
        __syncwarp();
        if ((g >> 1) == round) {
            float* st = ws + (g & 1) * SSTR;
            float4* stc = (float4*)(st + 36 * sub);       // 16B aligned
            #pragma unroll
            for (int q = 0; q < 9; ++q)
                stc[q] = *(const float4*)(cv + 4 * q);
            float4* stm = (float4*)(st + 288 + 12 * sub);
            #pragma unroll
            for (int q = 0; q < 3; ++q)
                stm[q] = *(const float4*)(mn + 4 * q);
        }
        __syncwarp();
        // warp-wide coalesced copy of 768 floats (2 vertices)
        float* outp = out + (size_t)(vbase + 2 * round) * 384;
        #pragma unroll
        for (int r = 0; r < 6; ++r) {
            const int e = r * 128 + lane * 4;
            const int gv = (e >= 384) ? 1 : 0;
            if (vbase + 2 * round + gv < V) {
                float4 val = *(const float4*)(ws + gv * SSTR + (e - gv * 384));
                *(float4*)(outp + e) = val;
            }
        }
    }
}

extern "C" void kernel_launch(void* const* d_in, const int* in_sizes, int n_in,
                              void* d_out, int out_size) {
    const float* coords = (const float*)d_in[0];   // V x 3
    const float* distsq = (const float*)d_in[1];   // V x 40
    const float* feats  = (const float*)d_in[2];   // V x 32
    const int*   nidx   = (const int*)d_in[3];     // V x 40
    float* out = (float*)d_out;                    // V x 384
    const int V = in_sizes[0] / 3;

    pad_coords_kernel<<<(V + 255) / 256, 256>>>(coords, V);

    const int vpb = VPW * WPB;                     // 16 vertices per block
    nbcov_kernel<<<(V + vpb - 1) / vpb, WPB * 32>>>(distsq, feats, nidx, out, V);
}